// round 14
// baseline (speedup 1.0000x reference)
#include <cuda_runtime.h>
#include <cuda_fp16.h>
#include <cstdint>
#include <math.h>

#define C_LEN 8192
#define Q_LEN 1024
#define D_DIM 1024

// ---------------- scratch (device globals) -----------------------------------
__device__ __align__(16) __half g_Hh[C_LEN * D_DIM];     // H (fp16 RN)
__device__ __align__(16) __half g_B1[Q_LEN * D_DIM];     // 32 * U * wqc (fp16 RN)
__device__ __align__(16) __half g_B2[D_DIM * Q_LEN];     // 16 * rz * U^T (fp16 RN)
__device__ __align__(16) __half g_e[C_LEN * Q_LEN];      // exp(s)/16 (fp16 RN)
__device__ __align__(16) float g_qterm[Q_LEN];
__device__ __align__(16) float g_cterm[C_LEN];
__device__ __align__(16) float g_bmax[C_LEN];
__device__ __align__(16) float g_colpart[64 * Q_LEN];
__device__ __align__(16) float g_hpart[128][D_DIM];
__device__ __align__(16) float g_hrow[D_DIM];

// ---------------- helpers -----------------------------------------------------
__device__ __forceinline__ uint32_t smem_u32(const void* p) {
    uint32_t a;
    asm("{ .reg .u64 t; cvta.to.shared.u64 t, %1; cvt.u32.u64 %0, t; }" : "=r"(a) : "l"(p));
    return a;
}
__device__ __forceinline__ void mma16816(float4& c, const uint32_t a[4],
                                         uint32_t b0, uint32_t b1) {
    asm volatile(
        "mma.sync.aligned.m16n8k16.row.col.f32.f16.f16.f32 "
        "{%0,%1,%2,%3}, {%4,%5,%6,%7}, {%8,%9}, {%0,%1,%2,%3};"
        : "+f"(c.x), "+f"(c.y), "+f"(c.z), "+f"(c.w)
        : "r"(a[0]), "r"(a[1]), "r"(a[2]), "r"(a[3]), "r"(b0), "r"(b1));
}
__device__ __forceinline__ void ldsm4(uint32_t d[4], uint32_t a) {
    asm volatile("ldmatrix.sync.aligned.m8n8.x4.shared.b16 {%0,%1,%2,%3}, [%4];"
                 : "=r"(d[0]), "=r"(d[1]), "=r"(d[2]), "=r"(d[3]) : "r"(a));
}
#define CP_ASYNC(d, s) asm volatile("cp.async.ca.shared.global [%0], [%1], 16;" :: "r"(d), "l"(s) : "memory")
#define CP_COMMIT()    asm volatile("cp.async.commit_group;" ::: "memory")
#define CP_WAIT1()     asm volatile("cp.async.wait_group 1;" ::: "memory")

__device__ __forceinline__ uint32_t h2_pack(float a, float b) {
    __half2 h = __floats2half2_rn(a, b);
    return *(uint32_t*)&h;
}

// ------ fused stats+split: blocks 0..8191 -> H row, 8192..9215 -> U row --------
__global__ void k_stats(const float* __restrict__ H, const float* __restrict__ U,
                        const float* __restrict__ wq, const float* __restrict__ bq,
                        const float* __restrict__ wc, const float* __restrict__ bc,
                        const float* __restrict__ wqc) {
    const int t = threadIdx.x;
    __shared__ float sp[8], sm2[8];
    if (blockIdx.x < C_LEN) {
        const int c = blockIdx.x;
        const int i = c * 1024 + t * 4;
        float4 h = *(const float4*)(H + i);
        float4 w = ((const float4*)wc)[t];
        *(uint2*)((uint16_t*)g_Hh + i) = make_uint2(h2_pack(h.x, h.y), h2_pack(h.z, h.w));
        float p = h.x * w.x + h.y * w.y + h.z * w.z + h.w * w.w;
        float m = fmaxf(fmaxf(h.x, h.y), fmaxf(h.z, h.w));
#pragma unroll
        for (int o = 16; o; o >>= 1) {
            p += __shfl_down_sync(0xffffffffu, p, o);
            m = fmaxf(m, __shfl_down_sync(0xffffffffu, m, o));
        }
        if ((t & 31) == 0) { sp[t >> 5] = p; sm2[t >> 5] = m; }
        __syncthreads();
        if (t == 0) {
            float pp = sp[0], mm = sm2[0];
#pragma unroll
            for (int i2 = 1; i2 < 8; ++i2) { pp += sp[i2]; mm = fmaxf(mm, sm2[i2]); }
            g_cterm[c] = pp + bc[0];
            g_bmax[c] = mm;
        }
    } else {
        const int n = blockIdx.x - C_LEN;
        const int i = n * 1024 + t * 4;
        float4 u = *(const float4*)(U + i);
        float4 w = ((const float4*)wq)[t];
        float p = u.x * w.x + u.y * w.y + u.z * w.z + u.w * w.w;
        float4 wq2 = ((const float4*)wqc)[t];
        *(uint2*)((uint16_t*)g_B1 + i) =
            make_uint2(h2_pack(32.f * u.x * wq2.x, 32.f * u.y * wq2.y),
                       h2_pack(32.f * u.z * wq2.z, 32.f * u.w * wq2.w));
#pragma unroll
        for (int o = 16; o; o >>= 1) p += __shfl_down_sync(0xffffffffu, p, o);
        if ((t & 31) == 0) sp[t >> 5] = p;
        __syncthreads();
        if (t == 0) {
            float s = sp[0];
#pragma unroll
            for (int i2 = 1; i2 < 8; ++i2) s += sp[i2];
            g_qterm[n] = s + bq[0];
        }
    }
}

// ------- prep: Z_q reduction + transpose B2 = 16 * rz * U^T (fused) ------------
__global__ void k_prep_ut(const float* __restrict__ U) {
    __shared__ float t[32][33];
    __shared__ float srz[32];
    const int tid = threadIdx.x;
    const int tx = tid & 31, ty = tid >> 5;
    const int d0 = blockIdx.x * 32, q0 = blockIdx.y * 32;
    if (tid < 32) {
        float s = 0.f;
#pragma unroll
        for (int i = 0; i < 64; ++i) s += g_colpart[i * 1024 + q0 + tid];
        srz[tid] = 16.f / s;
    }
#pragma unroll
    for (int i = 0; i < 4; ++i)
        t[ty + 8 * i][tx] = U[(size_t)(q0 + ty + 8 * i) * 1024 + d0 + tx];
    __syncthreads();
#pragma unroll
    for (int i = 0; i < 4; ++i) {
        const int d = d0 + ty + 8 * i;
        const float v = t[tx][ty + 8 * i] * srz[tx];
        ((__half*)g_B2)[(size_t)d * 1024 + q0 + tx] = __float2half_rn(v);
    }
}

// -------- GEMM: 3-stage cp.async, K=32/stage, 8 warps 64x32, 1 product --------
#define TS    16384u
#define O_B   8192u

__device__ __forceinline__ void fill_st(uint32_t sbuf, const __half* A, const __half* B,
                                        int m0, int n0, int k0, int t) {
#pragma unroll
    for (int u = 0; u < 2; ++u) {
        const int row = (t >> 2) + u * 64, ch = t & 3;
        const int chs = ch ^ ((row >> 1) & 3);
        const uint32_t d = sbuf + (uint32_t)(row * 64 + chs * 16);
        const size_t oa = (size_t)(m0 + row) * 1024 + k0 + ch * 8;
        const size_t ob = (size_t)(n0 + row) * 1024 + k0 + ch * 8;
        CP_ASYNC(d,       A + oa);
        CP_ASYNC(d + O_B, B + ob);
    }
}

// PASS=1: acc=32*s -> e=exp(s+..)/16 fp16 + col sums.
// PASS=2: store U_toggler fp32 + broadcast H_toggler slice.
template <int PASS>
__global__ __launch_bounds__(256, 2)
void k_mma(const __half* __restrict__ A, const __half* __restrict__ B,
           const float* __restrict__ bqc, float* __restrict__ out) {
    extern __shared__ char sm[];
    const uint32_t sb = smem_u32(sm);
    const int tid = threadIdx.x;
    const int lane = tid & 31, wid = tid >> 5;
    const int wm = wid & 1, wn = wid >> 1;
    const int g = lane >> 2, tq = lane & 3;
    const int m0 = blockIdx.y * 128, n0 = blockIdx.x * 128;
    const int lr = lane & 15, lc = lane >> 4;

    float4 acc[4][4];
#pragma unroll
    for (int i = 0; i < 4; ++i)
#pragma unroll
        for (int j = 0; j < 4; ++j) acc[i][j] = make_float4(0.f, 0.f, 0.f, 0.f);

    fill_st(sb, A, B, m0, n0, 0, tid);       CP_COMMIT();
    fill_st(sb + TS, A, B, m0, n0, 32, tid); CP_COMMIT();

    for (int s = 0; s < 32; ++s) {
        CP_WAIT1();
        __syncthreads();
        const uint32_t buf = sb + (uint32_t)(s % 3) * TS;

#pragma unroll
        for (int kk = 0; kk < 2; ++kk) {
            uint32_t af[4][4], bf[2][4];
#pragma unroll
            for (int mt = 0; mt < 4; ++mt) {
                const int row = wm * 64 + mt * 16 + lr;
                const int ch = kk * 2 + lc;
                const uint32_t off = (uint32_t)(row * 64 + ((ch ^ ((row >> 1) & 3)) * 16));
                ldsm4(af[mt], buf + off);
            }
#pragma unroll
            for (int nb = 0; nb < 2; ++nb) {
                const int row = wn * 32 + nb * 16 + lr;
                const int ch = kk * 2 + lc;
                const uint32_t off = (uint32_t)(row * 64 + ((ch ^ ((row >> 1) & 3)) * 16));
                ldsm4(bf[nb], buf + O_B + off);
            }
#pragma unroll
            for (int mt = 0; mt < 4; ++mt)
#pragma unroll
                for (int nt = 0; nt < 4; ++nt) {
                    const int nb = nt >> 1, p = nt & 1;
                    mma16816(acc[mt][nt], af[mt], bf[nb][p], bf[nb][p + 2]);
                }
        }

        if (s < 30)
            fill_st(sb + (uint32_t)((s + 2) % 3) * TS, A, B, m0, n0, (s + 2) * 32, tid);
        CP_COMMIT();
    }
    __syncthreads();

    if (PASS == 1) {
        const float bq = bqc[0];
        float* s_cp = (float*)sm;
        float cs[4][2];
#pragma unroll
        for (int nt = 0; nt < 4; ++nt) { cs[nt][0] = 0.f; cs[nt][1] = 0.f; }
#pragma unroll
        for (int mt = 0; mt < 4; ++mt) {
            const int row = m0 + wm * 64 + mt * 16 + g;
            const float ct0 = g_cterm[row], ct1 = g_cterm[row + 8];
#pragma unroll
            for (int nt = 0; nt < 4; ++nt) {
                const int col = n0 + wn * 32 + nt * 8 + tq * 2;
                const float q0 = g_qterm[col] + bq, q1 = g_qterm[col + 1] + bq;
                const float4 c = acc[mt][nt];
                const float e00 = __expf(c.x * 0.03125f + ct0 + q0);
                const float e01 = __expf(c.y * 0.03125f + ct0 + q1);
                const float e10 = __expf(c.z * 0.03125f + ct1 + q0);
                const float e11 = __expf(c.w * 0.03125f + ct1 + q1);
                const size_t o0 = (size_t)row * 1024 + col;
                const size_t o1 = (size_t)(row + 8) * 1024 + col;
                *(uint32_t*)((uint16_t*)g_e + o0) = h2_pack(e00 * 0.0625f, e01 * 0.0625f);
                *(uint32_t*)((uint16_t*)g_e + o1) = h2_pack(e10 * 0.0625f, e11 * 0.0625f);
                cs[nt][0] += e00 + e10;
                cs[nt][1] += e01 + e11;
            }
        }
#pragma unroll
        for (int nt = 0; nt < 4; ++nt)
#pragma unroll
            for (int o = 4; o < 32; o <<= 1) {
                cs[nt][0] += __shfl_xor_sync(0xffffffffu, cs[nt][0], o);
                cs[nt][1] += __shfl_xor_sync(0xffffffffu, cs[nt][1], o);
            }
        if (g == 0) {
#pragma unroll
            for (int nt = 0; nt < 4; ++nt) {
                const int col = wn * 32 + nt * 8 + tq * 2;
                s_cp[wm * 128 + col] = cs[nt][0];
                s_cp[wm * 128 + col + 1] = cs[nt][1];
            }
        }
        __syncthreads();
        if (tid < 128) {
            const float v = s_cp[tid] + s_cp[128 + tid];
            g_colpart[blockIdx.y * 1024 + n0 + tid] = v;
        }
    } else {
#pragma unroll
        for (int mt = 0; mt < 4; ++mt) {
            const int row = m0 + wm * 64 + mt * 16 + g;
#pragma unroll
            for (int nt = 0; nt < 4; ++nt) {
                const int col = n0 + wn * 32 + nt * 8 + tq * 2;
                const float4 c = acc[mt][nt];
                *(float2*)(out + (size_t)row * 1024 + col) = make_float2(c.x, c.y);
                *(float2*)(out + (size_t)(row + 8) * 1024 + col) = make_float2(c.z, c.w);
            }
        }
        // fused H_toggler broadcast: rows m0..m0+128, cols n0..n0+128
        const float4 hv = *(const float4*)(g_hrow + n0 + (tid & 31) * 4);
        float* o2 = out + (size_t)C_LEN * 1024;
#pragma unroll
        for (int r = tid >> 5; r < 128; r += 8)
            *(float4*)(o2 + (size_t)(m0 + r) * 1024 + n0 + (tid & 31) * 4) = hv;
    }
}

// ----- weighted column sum of H with in-block c2q softmax (128 chunks x 64 rows) --
__global__ void k_hpart(const float* __restrict__ H) {
    const int chunk = blockIdx.x, t = threadIdx.x;
    const int lane = t & 31, wid = t >> 5;
    __shared__ float sred[8];
    __shared__ float sbc[2];

    // in-block global softmax stats over g_bmax[8192] (fixed order, deterministic)
    float m = -1e30f;
    for (int c = t; c < C_LEN; c += 256) m = fmaxf(m, g_bmax[c]);
#pragma unroll
    for (int o = 16; o; o >>= 1) m = fmaxf(m, __shfl_xor_sync(0xffffffffu, m, o));
    if (lane == 0) sred[wid] = m;
    __syncthreads();
    if (t == 0) {
        float v = sred[0];
#pragma unroll
        for (int i = 1; i < 8; ++i) v = fmaxf(v, sred[i]);
        sbc[0] = v;
    }
    __syncthreads();
    const float mm = sbc[0];
    float z = 0.f;
    for (int c = t; c < C_LEN; c += 256) z += __expf(g_bmax[c] - mm);
#pragma unroll
    for (int o = 16; o; o >>= 1) z += __shfl_xor_sync(0xffffffffu, z, o);
    if (lane == 0) sred[wid] = z;
    __syncthreads();
    if (t == 0) {
        float v = sred[0];
#pragma unroll
        for (int i = 1; i < 8; ++i) v += sred[i];
        sbc[1] = 1.f / v;
    }
    __syncthreads();
    const float rz = sbc[1];

    float a0 = 0.f, a1 = 0.f, a2 = 0.f, a3 = 0.f;
    const int c0 = chunk * 64;
    for (int c = c0; c < c0 + 64; ++c) {
        const float wv = __expf(g_bmax[c] - mm) * rz;
        const float* hr = H + (size_t)c * 1024;
        a0 = fmaf(wv, hr[t], a0);
        a1 = fmaf(wv, hr[t + 256], a1);
        a2 = fmaf(wv, hr[t + 512], a2);
        a3 = fmaf(wv, hr[t + 768], a3);
    }
    g_hpart[chunk][t] = a0;
    g_hpart[chunk][t + 256] = a1;
    g_hpart[chunk][t + 512] = a2;
    g_hpart[chunk][t + 768] = a3;
}

__global__ void k_hred() {
    const int d = blockIdx.x * 64 + threadIdx.x;
    float s = 0.f;
#pragma unroll
    for (int i = 0; i < 128; ++i) s += g_hpart[i][d];
    g_hrow[d] = s;
}

// ---------------- launch ----------------------------------------------------------
extern "C" void kernel_launch(void* const* d_in, const int* in_sizes, int n_in,
                              void* d_out, int out_size) {
    const float* H   = (const float*)d_in[0];
    const float* U   = (const float*)d_in[1];
    const float* wq  = (const float*)d_in[2];
    const float* bq  = (const float*)d_in[3];
    const float* wc  = (const float*)d_in[4];
    const float* bc  = (const float*)d_in[5];
    const float* wqc = (const float*)d_in[6];
    const float* bqc = (const float*)d_in[7];
    float* out = (float*)d_out;

    static bool s_attr = false;
    if (!s_attr) {
        cudaFuncSetAttribute(k_mma<1>, cudaFuncAttributeMaxDynamicSharedMemorySize, 3 * TS);
        cudaFuncSetAttribute(k_mma<2>, cudaFuncAttributeMaxDynamicSharedMemorySize, 3 * TS);
        s_attr = true;
    }

    void *hh, *b1, *b2, *ee;
    cudaGetSymbolAddress(&hh, g_Hh);
    cudaGetSymbolAddress(&b1, g_B1);
    cudaGetSymbolAddress(&b2, g_B2);
    cudaGetSymbolAddress(&ee, g_e);

    k_stats<<<C_LEN + Q_LEN, 256>>>(H, U, wq, bq, wc, bc, wqc);
    k_mma<1><<<dim3(8, 64), 256, 3 * TS>>>((const __half*)hh, (const __half*)b1, bqc, nullptr);
    k_prep_ut<<<dim3(32, 32), 256>>>(U);
    k_hpart<<<128, 256>>>(H);
    k_hred<<<16, 64>>>();
    k_mma<2><<<dim3(8, 64), 256, 3 * TS>>>((const __half*)ee, (const __half*)b2, bqc, out);
}

// round 15
// speedup vs baseline: 1.0465x; 1.0465x over previous
#include <cuda_runtime.h>
#include <cuda_fp16.h>
#include <cstdint>
#include <math.h>

#define C_LEN 8192
#define Q_LEN 1024
#define D_DIM 1024

// ---------------- scratch (device globals) -----------------------------------
__device__ __align__(16) __half g_Hh[C_LEN * D_DIM];     // H (fp16 RN)
__device__ __align__(16) __half g_B1[Q_LEN * D_DIM];     // 32 * U * wqc (fp16 RN)
__device__ __align__(16) __half g_B2[D_DIM * Q_LEN];     // 16 * rz * U^T (fp16 RN)
__device__ __align__(16) __half g_e[C_LEN * Q_LEN];      // exp(s)/16 (fp16 RN)
__device__ __align__(16) float g_qterm[Q_LEN];
__device__ __align__(16) float g_cterm[C_LEN];
__device__ __align__(16) float g_bmax[C_LEN];
__device__ __align__(16) float g_colpart[64 * Q_LEN];
__device__ __align__(16) float g_hpart[256][D_DIM];
__device__ __align__(16) float g_hrow[D_DIM];

// ---------------- helpers -----------------------------------------------------
__device__ __forceinline__ uint32_t smem_u32(const void* p) {
    uint32_t a;
    asm("{ .reg .u64 t; cvta.to.shared.u64 t, %1; cvt.u32.u64 %0, t; }" : "=r"(a) : "l"(p));
    return a;
}
__device__ __forceinline__ void mma16816(float4& c, const uint32_t a[4],
                                         uint32_t b0, uint32_t b1) {
    asm volatile(
        "mma.sync.aligned.m16n8k16.row.col.f32.f16.f16.f32 "
        "{%0,%1,%2,%3}, {%4,%5,%6,%7}, {%8,%9}, {%0,%1,%2,%3};"
        : "+f"(c.x), "+f"(c.y), "+f"(c.z), "+f"(c.w)
        : "r"(a[0]), "r"(a[1]), "r"(a[2]), "r"(a[3]), "r"(b0), "r"(b1));
}
__device__ __forceinline__ void ldsm4(uint32_t d[4], uint32_t a) {
    asm volatile("ldmatrix.sync.aligned.m8n8.x4.shared.b16 {%0,%1,%2,%3}, [%4];"
                 : "=r"(d[0]), "=r"(d[1]), "=r"(d[2]), "=r"(d[3]) : "r"(a));
}
#define CP_ASYNC(d, s) asm volatile("cp.async.ca.shared.global [%0], [%1], 16;" :: "r"(d), "l"(s) : "memory")
#define CP_COMMIT()    asm volatile("cp.async.commit_group;" ::: "memory")
#define CP_WAIT1()     asm volatile("cp.async.wait_group 1;" ::: "memory")

__device__ __forceinline__ uint32_t h2_pack(float a, float b) {
    __half2 h = __floats2half2_rn(a, b);
    return *(uint32_t*)&h;
}

// ------ fused stats+split: blocks 0..8191 -> H row, 8192..9215 -> U row --------
__global__ void k_stats(const float* __restrict__ H, const float* __restrict__ U,
                        const float* __restrict__ wq, const float* __restrict__ bq,
                        const float* __restrict__ wc, const float* __restrict__ bc,
                        const float* __restrict__ wqc) {
    const int t = threadIdx.x;
    __shared__ float sp[8], sm2[8];
    if (blockIdx.x < C_LEN) {
        const int c = blockIdx.x;
        const int i = c * 1024 + t * 4;
        float4 h = *(const float4*)(H + i);
        float4 w = ((const float4*)wc)[t];
        *(uint2*)((uint16_t*)g_Hh + i) = make_uint2(h2_pack(h.x, h.y), h2_pack(h.z, h.w));
        float p = h.x * w.x + h.y * w.y + h.z * w.z + h.w * w.w;
        float m = fmaxf(fmaxf(h.x, h.y), fmaxf(h.z, h.w));
#pragma unroll
        for (int o = 16; o; o >>= 1) {
            p += __shfl_down_sync(0xffffffffu, p, o);
            m = fmaxf(m, __shfl_down_sync(0xffffffffu, m, o));
        }
        if ((t & 31) == 0) { sp[t >> 5] = p; sm2[t >> 5] = m; }
        __syncthreads();
        if (t == 0) {
            float pp = sp[0], mm = sm2[0];
#pragma unroll
            for (int i2 = 1; i2 < 8; ++i2) { pp += sp[i2]; mm = fmaxf(mm, sm2[i2]); }
            g_cterm[c] = pp + bc[0];
            g_bmax[c] = mm;
        }
    } else {
        const int n = blockIdx.x - C_LEN;
        const int i = n * 1024 + t * 4;
        float4 u = *(const float4*)(U + i);
        float4 w = ((const float4*)wq)[t];
        float p = u.x * w.x + u.y * w.y + u.z * w.z + u.w * w.w;
        float4 wq2 = ((const float4*)wqc)[t];
        *(uint2*)((uint16_t*)g_B1 + i) =
            make_uint2(h2_pack(32.f * u.x * wq2.x, 32.f * u.y * wq2.y),
                       h2_pack(32.f * u.z * wq2.z, 32.f * u.w * wq2.w));
#pragma unroll
        for (int o = 16; o; o >>= 1) p += __shfl_down_sync(0xffffffffu, p, o);
        if ((t & 31) == 0) sp[t >> 5] = p;
        __syncthreads();
        if (t == 0) {
            float s = sp[0];
#pragma unroll
            for (int i2 = 1; i2 < 8; ++i2) s += sp[i2];
            g_qterm[n] = s + bq[0];
        }
    }
}

// ------- prep: Z_q reduction + transpose B2 = 16 * rz * U^T (fused) ------------
__global__ void k_prep_ut(const float* __restrict__ U) {
    __shared__ float t[32][33];
    __shared__ float srz[32];
    const int tid = threadIdx.x;
    const int tx = tid & 31, ty = tid >> 5;
    const int d0 = blockIdx.x * 32, q0 = blockIdx.y * 32;
    if (tid < 32) {
        float s = 0.f;
#pragma unroll
        for (int i = 0; i < 64; ++i) s += g_colpart[i * 1024 + q0 + tid];
        srz[tid] = 16.f / s;
    }
#pragma unroll
    for (int i = 0; i < 4; ++i)
        t[ty + 8 * i][tx] = U[(size_t)(q0 + ty + 8 * i) * 1024 + d0 + tx];
    __syncthreads();
#pragma unroll
    for (int i = 0; i < 4; ++i) {
        const int d = d0 + ty + 8 * i;
        const float v = t[tx][ty + 8 * i] * srz[tx];
        ((__half*)g_B2)[(size_t)d * 1024 + q0 + tx] = __float2half_rn(v);
    }
}

// -------- GEMM: 3-stage cp.async, K=32/stage, 8 warps 64x32, 1 product --------
#define TS    16384u
#define O_B   8192u

__device__ __forceinline__ void fill_st(uint32_t sbuf, const __half* A, const __half* B,
                                        int m0, int n0, int k0, int t) {
#pragma unroll
    for (int u = 0; u < 2; ++u) {
        const int row = (t >> 2) + u * 64, ch = t & 3;
        const int chs = ch ^ ((row >> 1) & 3);
        const uint32_t d = sbuf + (uint32_t)(row * 64 + chs * 16);
        const size_t oa = (size_t)(m0 + row) * 1024 + k0 + ch * 8;
        const size_t ob = (size_t)(n0 + row) * 1024 + k0 + ch * 8;
        CP_ASYNC(d,       A + oa);
        CP_ASYNC(d + O_B, B + ob);
    }
}

// PASS=1: acc=32*s -> e=exp(s+..)/16 fp16 + col sums.
// PASS=2: store U_toggler fp32 + broadcast H_toggler slice.
template <int PASS>
__global__ __launch_bounds__(256, 2)
void k_mma(const __half* __restrict__ A, const __half* __restrict__ B,
           const float* __restrict__ bqc, float* __restrict__ out) {
    extern __shared__ char sm[];
    const uint32_t sb = smem_u32(sm);
    const int tid = threadIdx.x;
    const int lane = tid & 31, wid = tid >> 5;
    const int wm = wid & 1, wn = wid >> 1;
    const int g = lane >> 2, tq = lane & 3;
    const int m0 = blockIdx.y * 128, n0 = blockIdx.x * 128;
    const int lr = lane & 15, lc = lane >> 4;

    float4 acc[4][4];
#pragma unroll
    for (int i = 0; i < 4; ++i)
#pragma unroll
        for (int j = 0; j < 4; ++j) acc[i][j] = make_float4(0.f, 0.f, 0.f, 0.f);

    fill_st(sb, A, B, m0, n0, 0, tid);       CP_COMMIT();
    fill_st(sb + TS, A, B, m0, n0, 32, tid); CP_COMMIT();

    for (int s = 0; s < 32; ++s) {
        CP_WAIT1();
        __syncthreads();
        const uint32_t buf = sb + (uint32_t)(s % 3) * TS;

#pragma unroll
        for (int kk = 0; kk < 2; ++kk) {
            uint32_t af[4][4], bf[2][4];
#pragma unroll
            for (int mt = 0; mt < 4; ++mt) {
                const int row = wm * 64 + mt * 16 + lr;
                const int ch = kk * 2 + lc;
                const uint32_t off = (uint32_t)(row * 64 + ((ch ^ ((row >> 1) & 3)) * 16));
                ldsm4(af[mt], buf + off);
            }
#pragma unroll
            for (int nb = 0; nb < 2; ++nb) {
                const int row = wn * 32 + nb * 16 + lr;
                const int ch = kk * 2 + lc;
                const uint32_t off = (uint32_t)(row * 64 + ((ch ^ ((row >> 1) & 3)) * 16));
                ldsm4(bf[nb], buf + O_B + off);
            }
#pragma unroll
            for (int mt = 0; mt < 4; ++mt)
#pragma unroll
                for (int nt = 0; nt < 4; ++nt) {
                    const int nb = nt >> 1, p = nt & 1;
                    mma16816(acc[mt][nt], af[mt], bf[nb][p], bf[nb][p + 2]);
                }
        }

        if (s < 30)
            fill_st(sb + (uint32_t)((s + 2) % 3) * TS, A, B, m0, n0, (s + 2) * 32, tid);
        CP_COMMIT();
    }
    __syncthreads();

    if (PASS == 1) {
        const float bq = bqc[0];
        float* s_cp = (float*)sm;
        float cs[4][2];
#pragma unroll
        for (int nt = 0; nt < 4; ++nt) { cs[nt][0] = 0.f; cs[nt][1] = 0.f; }
#pragma unroll
        for (int mt = 0; mt < 4; ++mt) {
            const int row = m0 + wm * 64 + mt * 16 + g;
            const float ct0 = g_cterm[row], ct1 = g_cterm[row + 8];
#pragma unroll
            for (int nt = 0; nt < 4; ++nt) {
                const int col = n0 + wn * 32 + nt * 8 + tq * 2;
                const float q0 = g_qterm[col] + bq, q1 = g_qterm[col + 1] + bq;
                const float4 c = acc[mt][nt];
                const float e00 = __expf(c.x * 0.03125f + ct0 + q0);
                const float e01 = __expf(c.y * 0.03125f + ct0 + q1);
                const float e10 = __expf(c.z * 0.03125f + ct1 + q0);
                const float e11 = __expf(c.w * 0.03125f + ct1 + q1);
                const size_t o0 = (size_t)row * 1024 + col;
                const size_t o1 = (size_t)(row + 8) * 1024 + col;
                *(uint32_t*)((uint16_t*)g_e + o0) = h2_pack(e00 * 0.0625f, e01 * 0.0625f);
                *(uint32_t*)((uint16_t*)g_e + o1) = h2_pack(e10 * 0.0625f, e11 * 0.0625f);
                cs[nt][0] += e00 + e10;
                cs[nt][1] += e01 + e11;
            }
        }
#pragma unroll
        for (int nt = 0; nt < 4; ++nt)
#pragma unroll
            for (int o = 4; o < 32; o <<= 1) {
                cs[nt][0] += __shfl_xor_sync(0xffffffffu, cs[nt][0], o);
                cs[nt][1] += __shfl_xor_sync(0xffffffffu, cs[nt][1], o);
            }
        if (g == 0) {
#pragma unroll
            for (int nt = 0; nt < 4; ++nt) {
                const int col = wn * 32 + nt * 8 + tq * 2;
                s_cp[wm * 128 + col] = cs[nt][0];
                s_cp[wm * 128 + col + 1] = cs[nt][1];
            }
        }
        __syncthreads();
        if (tid < 128) {
            const float v = s_cp[tid] + s_cp[128 + tid];
            g_colpart[blockIdx.y * 1024 + n0 + tid] = v;
        }
    } else {
#pragma unroll
        for (int mt = 0; mt < 4; ++mt) {
            const int row = m0 + wm * 64 + mt * 16 + g;
#pragma unroll
            for (int nt = 0; nt < 4; ++nt) {
                const int col = n0 + wn * 32 + nt * 8 + tq * 2;
                const float4 c = acc[mt][nt];
                *(float2*)(out + (size_t)row * 1024 + col) = make_float2(c.x, c.y);
                *(float2*)(out + (size_t)(row + 8) * 1024 + col) = make_float2(c.z, c.w);
            }
        }
        // fused H_toggler broadcast: rows m0..m0+128, cols n0..n0+128
        const float4 hv = *(const float4*)(g_hrow + n0 + (tid & 31) * 4);
        float* o2 = out + (size_t)C_LEN * 1024;
#pragma unroll
        for (int r = tid >> 5; r < 128; r += 8)
            *(float4*)(o2 + (size_t)(m0 + r) * 1024 + n0 + (tid & 31) * 4) = hv;
    }
}

// ----- weighted column sum of H with in-block c2q softmax (256 chunks x 32 rows) --
__global__ void k_hpart(const float* __restrict__ H) {
    const int chunk = blockIdx.x, t = threadIdx.x;
    const int lane = t & 31, wid = t >> 5;
    __shared__ float sred[8];
    __shared__ float sbc[2];

    // in-block global softmax stats over g_bmax[8192] (fixed order, deterministic)
    float m = -1e30f;
    for (int c = t; c < C_LEN; c += 256) m = fmaxf(m, g_bmax[c]);
#pragma unroll
    for (int o = 16; o; o >>= 1) m = fmaxf(m, __shfl_xor_sync(0xffffffffu, m, o));
    if (lane == 0) sred[wid] = m;
    __syncthreads();
    if (t == 0) {
        float v = sred[0];
#pragma unroll
        for (int i = 1; i < 8; ++i) v = fmaxf(v, sred[i]);
        sbc[0] = v;
    }
    __syncthreads();
    const float mm = sbc[0];
    float z = 0.f;
    for (int c = t; c < C_LEN; c += 256) z += __expf(g_bmax[c] - mm);
#pragma unroll
    for (int o = 16; o; o >>= 1) z += __shfl_xor_sync(0xffffffffu, z, o);
    if (lane == 0) sred[wid] = z;
    __syncthreads();
    if (t == 0) {
        float v = sred[0];
#pragma unroll
        for (int i = 1; i < 8; ++i) v += sred[i];
        sbc[1] = 1.f / v;
    }
    __syncthreads();
    const float rz = sbc[1];

    // 32 rows, float4 per thread per row, unroll 4 for MLP
    float4 a = make_float4(0.f, 0.f, 0.f, 0.f);
    const int c0 = chunk * 32;
#pragma unroll 4
    for (int c = c0; c < c0 + 32; ++c) {
        const float wv = __expf(g_bmax[c] - mm) * rz;
        const float4 h = *(const float4*)(H + (size_t)c * 1024 + t * 4);
        a.x = fmaf(wv, h.x, a.x);
        a.y = fmaf(wv, h.y, a.y);
        a.z = fmaf(wv, h.z, a.z);
        a.w = fmaf(wv, h.w, a.w);
    }
    *(float4*)(&g_hpart[chunk][t * 4]) = a;
}

__global__ void k_hred() {
    const int d = blockIdx.x * 64 + threadIdx.x;
    float s = 0.f;
#pragma unroll
    for (int i = 0; i < 256; ++i) s += g_hpart[i][d];
    g_hrow[d] = s;
}

// ---------------- launch ----------------------------------------------------------
extern "C" void kernel_launch(void* const* d_in, const int* in_sizes, int n_in,
                              void* d_out, int out_size) {
    const float* H   = (const float*)d_in[0];
    const float* U   = (const float*)d_in[1];
    const float* wq  = (const float*)d_in[2];
    const float* bq  = (const float*)d_in[3];
    const float* wc  = (const float*)d_in[4];
    const float* bc  = (const float*)d_in[5];
    const float* wqc = (const float*)d_in[6];
    const float* bqc = (const float*)d_in[7];
    float* out = (float*)d_out;

    static bool s_attr = false;
    if (!s_attr) {
        cudaFuncSetAttribute(k_mma<1>, cudaFuncAttributeMaxDynamicSharedMemorySize, 3 * TS);
        cudaFuncSetAttribute(k_mma<2>, cudaFuncAttributeMaxDynamicSharedMemorySize, 3 * TS);
        s_attr = true;
    }

    void *hh, *b1, *b2, *ee;
    cudaGetSymbolAddress(&hh, g_Hh);
    cudaGetSymbolAddress(&b1, g_B1);
    cudaGetSymbolAddress(&b2, g_B2);
    cudaGetSymbolAddress(&ee, g_e);

    k_stats<<<C_LEN + Q_LEN, 256>>>(H, U, wq, bq, wc, bc, wqc);
    k_mma<1><<<dim3(8, 64), 256, 3 * TS>>>((const __half*)hh, (const __half*)b1, bqc, nullptr);
    k_prep_ut<<<dim3(32, 32), 256>>>(U);
    k_hpart<<<256, 256>>>(H);
    k_hred<<<16, 64>>>();
    k_mma<2><<<dim3(8, 64), 256, 3 * TS>>>((const __half*)ee, (const __half*)b2, bqc, out);
}

// round 16
// speedup vs baseline: 1.0722x; 1.0246x over previous
#include <cuda_runtime.h>
#include <cuda_fp16.h>
#include <cstdint>
#include <math.h>

#define C_LEN 8192
#define Q_LEN 1024
#define D_DIM 1024

// ---------------- scratch (device globals) -----------------------------------
__device__ __align__(16) __half g_Hh[C_LEN * D_DIM];     // H (fp16 RN)
__device__ __align__(16) __half g_B1[Q_LEN * D_DIM];     // 32 * U * wqc (fp16 RN)
__device__ __align__(16) __half g_B2[D_DIM * Q_LEN];     // 16 * rz * U^T (fp16 RN)
__device__ __align__(16) __half g_e[C_LEN * Q_LEN];      // exp(s)/16 (fp16 RN)
__device__ __align__(16) float g_qterm[Q_LEN];
__device__ __align__(16) float g_cterm[C_LEN];
__device__ __align__(16) float g_bmax[C_LEN];
__device__ __align__(16) float g_colpart[64 * Q_LEN];
__device__ __align__(16) float g_mz[2];                  // c2q softmax {max, 1/Z}
__device__ __align__(16) float g_hpart[256][D_DIM];
__device__ __align__(16) float g_hrow[D_DIM];

// ---------------- helpers -----------------------------------------------------
__device__ __forceinline__ uint32_t smem_u32(const void* p) {
    uint32_t a;
    asm("{ .reg .u64 t; cvta.to.shared.u64 t, %1; cvt.u32.u64 %0, t; }" : "=r"(a) : "l"(p));
    return a;
}
__device__ __forceinline__ void mma16816(float4& c, const uint32_t a[4],
                                         uint32_t b0, uint32_t b1) {
    asm volatile(
        "mma.sync.aligned.m16n8k16.row.col.f32.f16.f16.f32 "
        "{%0,%1,%2,%3}, {%4,%5,%6,%7}, {%8,%9}, {%0,%1,%2,%3};"
        : "+f"(c.x), "+f"(c.y), "+f"(c.z), "+f"(c.w)
        : "r"(a[0]), "r"(a[1]), "r"(a[2]), "r"(a[3]), "r"(b0), "r"(b1));
}
__device__ __forceinline__ void ldsm4(uint32_t d[4], uint32_t a) {
    asm volatile("ldmatrix.sync.aligned.m8n8.x4.shared.b16 {%0,%1,%2,%3}, [%4];"
                 : "=r"(d[0]), "=r"(d[1]), "=r"(d[2]), "=r"(d[3]) : "r"(a));
}
#define CP_ASYNC(d, s) asm volatile("cp.async.ca.shared.global [%0], [%1], 16;" :: "r"(d), "l"(s) : "memory")
#define CP_COMMIT()    asm volatile("cp.async.commit_group;" ::: "memory")
#define CP_WAIT1()     asm volatile("cp.async.wait_group 1;" ::: "memory")

__device__ __forceinline__ uint32_t h2_pack(float a, float b) {
    __half2 h = __floats2half2_rn(a, b);
    return *(uint32_t*)&h;
}

// ------ fused stats+split: blocks 0..8191 -> H row, 8192..9215 -> U row --------
__global__ void k_stats(const float* __restrict__ H, const float* __restrict__ U,
                        const float* __restrict__ wq, const float* __restrict__ bq,
                        const float* __restrict__ wc, const float* __restrict__ bc,
                        const float* __restrict__ wqc) {
    const int t = threadIdx.x;
    __shared__ float sp[8], sm2[8];
    if (blockIdx.x < C_LEN) {
        const int c = blockIdx.x;
        const int i = c * 1024 + t * 4;
        float4 h = *(const float4*)(H + i);
        float4 w = ((const float4*)wc)[t];
        *(uint2*)((uint16_t*)g_Hh + i) = make_uint2(h2_pack(h.x, h.y), h2_pack(h.z, h.w));
        float p = h.x * w.x + h.y * w.y + h.z * w.z + h.w * w.w;
        float m = fmaxf(fmaxf(h.x, h.y), fmaxf(h.z, h.w));
#pragma unroll
        for (int o = 16; o; o >>= 1) {
            p += __shfl_down_sync(0xffffffffu, p, o);
            m = fmaxf(m, __shfl_down_sync(0xffffffffu, m, o));
        }
        if ((t & 31) == 0) { sp[t >> 5] = p; sm2[t >> 5] = m; }
        __syncthreads();
        if (t == 0) {
            float pp = sp[0], mm = sm2[0];
#pragma unroll
            for (int i2 = 1; i2 < 8; ++i2) { pp += sp[i2]; mm = fmaxf(mm, sm2[i2]); }
            g_cterm[c] = pp + bc[0];
            g_bmax[c] = mm;
        }
    } else {
        const int n = blockIdx.x - C_LEN;
        const int i = n * 1024 + t * 4;
        float4 u = *(const float4*)(U + i);
        float4 w = ((const float4*)wq)[t];
        float p = u.x * w.x + u.y * w.y + u.z * w.z + u.w * w.w;
        float4 wq2 = ((const float4*)wqc)[t];
        *(uint2*)((uint16_t*)g_B1 + i) =
            make_uint2(h2_pack(32.f * u.x * wq2.x, 32.f * u.y * wq2.y),
                       h2_pack(32.f * u.z * wq2.z, 32.f * u.w * wq2.w));
#pragma unroll
        for (int o = 16; o; o >>= 1) p += __shfl_down_sync(0xffffffffu, p, o);
        if ((t & 31) == 0) sp[t >> 5] = p;
        __syncthreads();
        if (t == 0) {
            float s = sp[0];
#pragma unroll
            for (int i2 = 1; i2 < 8; ++i2) s += sp[i2];
            g_qterm[n] = s + bq[0];
        }
    }
}

// ------- prep: Z_q reduction + transpose B2 = 16 * rz * U^T; block(0,0) also
//         computes the c2q softmax scalars {M, 1/Z} into g_mz ------------------
__global__ void k_prep_ut(const float* __restrict__ U) {
    __shared__ float t[32][33];
    __shared__ float srz[32];
    const int tid = threadIdx.x;
    const int tx = tid & 31, ty = tid >> 5;
    const int d0 = blockIdx.x * 32, q0 = blockIdx.y * 32;
    if (tid < 32) {
        float s = 0.f;
#pragma unroll
        for (int i = 0; i < 64; ++i) s += g_colpart[i * 1024 + q0 + tid];
        srz[tid] = 16.f / s;
    }
#pragma unroll
    for (int i = 0; i < 4; ++i)
        t[ty + 8 * i][tx] = U[(size_t)(q0 + ty + 8 * i) * 1024 + d0 + tx];
    __syncthreads();
#pragma unroll
    for (int i = 0; i < 4; ++i) {
        const int d = d0 + ty + 8 * i;
        const float v = t[tx][ty + 8 * i] * srz[tx];
        ((__half*)g_B2)[(size_t)d * 1024 + q0 + tx] = __float2half_rn(v);
    }

    // one block computes global softmax scalars over g_bmax[8192]
    if (blockIdx.x == 0 && blockIdx.y == 0) {
        __shared__ float sred[8];
        __shared__ float sm;
        const int lane = tid & 31, wid = tid >> 5;
        float m = -1e30f;
        for (int c = tid; c < C_LEN; c += 256) m = fmaxf(m, g_bmax[c]);
#pragma unroll
        for (int o = 16; o; o >>= 1) m = fmaxf(m, __shfl_xor_sync(0xffffffffu, m, o));
        if (lane == 0) sred[wid] = m;
        __syncthreads();
        if (tid == 0) {
            float v = sred[0];
#pragma unroll
            for (int i = 1; i < 8; ++i) v = fmaxf(v, sred[i]);
            sm = v;
        }
        __syncthreads();
        const float mm = sm;
        float z = 0.f;
        for (int c = tid; c < C_LEN; c += 256) z += __expf(g_bmax[c] - mm);
#pragma unroll
        for (int o = 16; o; o >>= 1) z += __shfl_xor_sync(0xffffffffu, z, o);
        if (lane == 0) sred[wid] = z;
        __syncthreads();
        if (tid == 0) {
            float v = sred[0];
#pragma unroll
            for (int i = 1; i < 8; ++i) v += sred[i];
            g_mz[0] = mm;
            g_mz[1] = 1.f / v;
        }
    }
}

// -------- GEMM: 3-stage cp.async, K=32/stage, 8 warps 64x32, 1 product --------
#define TS    16384u
#define O_B   8192u

__device__ __forceinline__ void fill_st(uint32_t sbuf, const __half* A, const __half* B,
                                        int m0, int n0, int k0, int t) {
#pragma unroll
    for (int u = 0; u < 2; ++u) {
        const int row = (t >> 2) + u * 64, ch = t & 3;
        const int chs = ch ^ ((row >> 1) & 3);
        const uint32_t d = sbuf + (uint32_t)(row * 64 + chs * 16);
        const size_t oa = (size_t)(m0 + row) * 1024 + k0 + ch * 8;
        const size_t ob = (size_t)(n0 + row) * 1024 + k0 + ch * 8;
        CP_ASYNC(d,       A + oa);
        CP_ASYNC(d + O_B, B + ob);
    }
}

// PASS=1: acc=32*s -> e=exp(s+..)/16 fp16 + col sums.
// PASS=2: store U_toggler fp32 + broadcast H_toggler slice.
template <int PASS>
__global__ __launch_bounds__(256, 2)
void k_mma(const __half* __restrict__ A, const __half* __restrict__ B,
           const float* __restrict__ bqc, float* __restrict__ out) {
    extern __shared__ char sm[];
    const uint32_t sb = smem_u32(sm);
    const int tid = threadIdx.x;
    const int lane = tid & 31, wid = tid >> 5;
    const int wm = wid & 1, wn = wid >> 1;
    const int g = lane >> 2, tq = lane & 3;
    const int m0 = blockIdx.y * 128, n0 = blockIdx.x * 128;
    const int lr = lane & 15, lc = lane >> 4;

    float4 acc[4][4];
#pragma unroll
    for (int i = 0; i < 4; ++i)
#pragma unroll
        for (int j = 0; j < 4; ++j) acc[i][j] = make_float4(0.f, 0.f, 0.f, 0.f);

    fill_st(sb, A, B, m0, n0, 0, tid);       CP_COMMIT();
    fill_st(sb + TS, A, B, m0, n0, 32, tid); CP_COMMIT();

    for (int s = 0; s < 32; ++s) {
        CP_WAIT1();
        __syncthreads();
        const uint32_t buf = sb + (uint32_t)(s % 3) * TS;

#pragma unroll
        for (int kk = 0; kk < 2; ++kk) {
            uint32_t af[4][4], bf[2][4];
#pragma unroll
            for (int mt = 0; mt < 4; ++mt) {
                const int row = wm * 64 + mt * 16 + lr;
                const int ch = kk * 2 + lc;
                const uint32_t off = (uint32_t)(row * 64 + ((ch ^ ((row >> 1) & 3)) * 16));
                ldsm4(af[mt], buf + off);
            }
#pragma unroll
            for (int nb = 0; nb < 2; ++nb) {
                const int row = wn * 32 + nb * 16 + lr;
                const int ch = kk * 2 + lc;
                const uint32_t off = (uint32_t)(row * 64 + ((ch ^ ((row >> 1) & 3)) * 16));
                ldsm4(bf[nb], buf + O_B + off);
            }
#pragma unroll
            for (int mt = 0; mt < 4; ++mt)
#pragma unroll
                for (int nt = 0; nt < 4; ++nt) {
                    const int nb = nt >> 1, p = nt & 1;
                    mma16816(acc[mt][nt], af[mt], bf[nb][p], bf[nb][p + 2]);
                }
        }

        if (s < 30)
            fill_st(sb + (uint32_t)((s + 2) % 3) * TS, A, B, m0, n0, (s + 2) * 32, tid);
        CP_COMMIT();
    }
    __syncthreads();

    if (PASS == 1) {
        const float bq = bqc[0];
        float* s_cp = (float*)sm;
        float cs[4][2];
#pragma unroll
        for (int nt = 0; nt < 4; ++nt) { cs[nt][0] = 0.f; cs[nt][1] = 0.f; }
#pragma unroll
        for (int mt = 0; mt < 4; ++mt) {
            const int row = m0 + wm * 64 + mt * 16 + g;
            const float ct0 = g_cterm[row], ct1 = g_cterm[row + 8];
#pragma unroll
            for (int nt = 0; nt < 4; ++nt) {
                const int col = n0 + wn * 32 + nt * 8 + tq * 2;
                const float q0 = g_qterm[col] + bq, q1 = g_qterm[col + 1] + bq;
                const float4 c = acc[mt][nt];
                const float e00 = __expf(c.x * 0.03125f + ct0 + q0);
                const float e01 = __expf(c.y * 0.03125f + ct0 + q1);
                const float e10 = __expf(c.z * 0.03125f + ct1 + q0);
                const float e11 = __expf(c.w * 0.03125f + ct1 + q1);
                const size_t o0 = (size_t)row * 1024 + col;
                const size_t o1 = (size_t)(row + 8) * 1024 + col;
                *(uint32_t*)((uint16_t*)g_e + o0) = h2_pack(e00 * 0.0625f, e01 * 0.0625f);
                *(uint32_t*)((uint16_t*)g_e + o1) = h2_pack(e10 * 0.0625f, e11 * 0.0625f);
                cs[nt][0] += e00 + e10;
                cs[nt][1] += e01 + e11;
            }
        }
#pragma unroll
        for (int nt = 0; nt < 4; ++nt)
#pragma unroll
            for (int o = 4; o < 32; o <<= 1) {
                cs[nt][0] += __shfl_xor_sync(0xffffffffu, cs[nt][0], o);
                cs[nt][1] += __shfl_xor_sync(0xffffffffu, cs[nt][1], o);
            }
        if (g == 0) {
#pragma unroll
            for (int nt = 0; nt < 4; ++nt) {
                const int col = wn * 32 + nt * 8 + tq * 2;
                s_cp[wm * 128 + col] = cs[nt][0];
                s_cp[wm * 128 + col + 1] = cs[nt][1];
            }
        }
        __syncthreads();
        if (tid < 128) {
            const float v = s_cp[tid] + s_cp[128 + tid];
            g_colpart[blockIdx.y * 1024 + n0 + tid] = v;
        }
    } else {
#pragma unroll
        for (int mt = 0; mt < 4; ++mt) {
            const int row = m0 + wm * 64 + mt * 16 + g;
#pragma unroll
            for (int nt = 0; nt < 4; ++nt) {
                const int col = n0 + wn * 32 + nt * 8 + tq * 2;
                const float4 c = acc[mt][nt];
                *(float2*)(out + (size_t)row * 1024 + col) = make_float2(c.x, c.y);
                *(float2*)(out + (size_t)(row + 8) * 1024 + col) = make_float2(c.z, c.w);
            }
        }
        // fused H_toggler broadcast
        const float4 hv = *(const float4*)(g_hrow + n0 + (tid & 31) * 4);
        float* o2 = out + (size_t)C_LEN * 1024;
#pragma unroll
        for (int r = tid >> 5; r < 128; r += 8)
            *(float4*)(o2 + (size_t)(m0 + r) * 1024 + n0 + (tid & 31) * 4) = hv;
    }
}

// ----- weighted column sum of fp16 H (256 chunks x 32 rows), scalars hoisted -----
__global__ void k_hpart() {
    const int chunk = blockIdx.x, t = threadIdx.x;
    const float mm = g_mz[0], rz = g_mz[1];
    float4 a = make_float4(0.f, 0.f, 0.f, 0.f);
    const int c0 = chunk * 32;
#pragma unroll 4
    for (int c = c0; c < c0 + 32; ++c) {
        const float wv = __expf(g_bmax[c] - mm) * rz;
        const uint2 hv = *(const uint2*)((const uint16_t*)g_Hh + (size_t)c * 1024 + t * 4);
        const float2 h01 = __half22float2(*(const __half2*)&hv.x);
        const float2 h23 = __half22float2(*(const __half2*)&hv.y);
        a.x = fmaf(wv, h01.x, a.x);
        a.y = fmaf(wv, h01.y, a.y);
        a.z = fmaf(wv, h23.x, a.z);
        a.w = fmaf(wv, h23.y, a.w);
    }
    *(float4*)(&g_hpart[chunk][t * 4]) = a;
}

__global__ void k_hred() {
    const int d = blockIdx.x * 64 + threadIdx.x;
    float s = 0.f;
#pragma unroll
    for (int i = 0; i < 256; ++i) s += g_hpart[i][d];
    g_hrow[d] = s;
}

// ---------------- launch ----------------------------------------------------------
extern "C" void kernel_launch(void* const* d_in, const int* in_sizes, int n_in,
                              void* d_out, int out_size) {
    const float* H   = (const float*)d_in[0];
    const float* U   = (const float*)d_in[1];
    const float* wq  = (const float*)d_in[2];
    const float* bq  = (const float*)d_in[3];
    const float* wc  = (const float*)d_in[4];
    const float* bc  = (const float*)d_in[5];
    const float* wqc = (const float*)d_in[6];
    const float* bqc = (const float*)d_in[7];
    float* out = (float*)d_out;

    static bool s_attr = false;
    if (!s_attr) {
        cudaFuncSetAttribute(k_mma<1>, cudaFuncAttributeMaxDynamicSharedMemorySize, 3 * TS);
        cudaFuncSetAttribute(k_mma<2>, cudaFuncAttributeMaxDynamicSharedMemorySize, 3 * TS);
        s_attr = true;
    }

    void *hh, *b1, *b2, *ee;
    cudaGetSymbolAddress(&hh, g_Hh);
    cudaGetSymbolAddress(&b1, g_B1);
    cudaGetSymbolAddress(&b2, g_B2);
    cudaGetSymbolAddress(&ee, g_e);

    k_stats<<<C_LEN + Q_LEN, 256>>>(H, U, wq, bq, wc, bc, wqc);
    k_mma<1><<<dim3(8, 64), 256, 3 * TS>>>((const __half*)hh, (const __half*)b1, bqc, nullptr);
    k_prep_ut<<<dim3(32, 32), 256>>>(U);
    k_hpart<<<256, 256>>>();
    k_hred<<<16, 64>>>();
    k_mma<2><<<dim3(8, 64), 256, 3 * TS>>>((const __half*)ee, (const __half*)b2, bqc, out);
}

// round 17
// speedup vs baseline: 1.0820x; 1.0091x over previous
#include <cuda_runtime.h>
#include <cuda_fp16.h>
#include <cstdint>
#include <math.h>

#define C_LEN 8192
#define Q_LEN 1024
#define D_DIM 1024

// ---------------- scratch (device globals) -----------------------------------
__device__ __align__(16) __half g_Hh[C_LEN * D_DIM];     // H (fp16 RN)
__device__ __align__(16) __half g_B1[Q_LEN * D_DIM];     // 32 * U * wqc (fp16 RN)
__device__ __align__(16) __half g_B2[D_DIM * Q_LEN];     // 16 * rz * U^T (fp16 RN)
__device__ __align__(16) __half g_e[C_LEN * Q_LEN];      // exp(s)/16 (fp16 RN)
__device__ __align__(16) float g_qterm[Q_LEN];
__device__ __align__(16) float g_cterm[C_LEN];
__device__ __align__(16) float g_bmax[C_LEN];
__device__ __align__(16) float g_colpart[64 * Q_LEN];
__device__ __align__(16) float g_mz[2];                  // c2q softmax {max, 1/Z}
__device__ __align__(16) float g_hpart[256][D_DIM];
__device__ __align__(16) float g_hrow[D_DIM];

// ---------------- helpers -----------------------------------------------------
__device__ __forceinline__ uint32_t smem_u32(const void* p) {
    uint32_t a;
    asm("{ .reg .u64 t; cvta.to.shared.u64 t, %1; cvt.u32.u64 %0, t; }" : "=r"(a) : "l"(p));
    return a;
}
__device__ __forceinline__ void mma16816(float4& c, const uint32_t a[4],
                                         uint32_t b0, uint32_t b1) {
    asm volatile(
        "mma.sync.aligned.m16n8k16.row.col.f32.f16.f16.f32 "
        "{%0,%1,%2,%3}, {%4,%5,%6,%7}, {%8,%9}, {%0,%1,%2,%3};"
        : "+f"(c.x), "+f"(c.y), "+f"(c.z), "+f"(c.w)
        : "r"(a[0]), "r"(a[1]), "r"(a[2]), "r"(a[3]), "r"(b0), "r"(b1));
}
__device__ __forceinline__ void ldsm4(uint32_t d[4], uint32_t a) {
    asm volatile("ldmatrix.sync.aligned.m8n8.x4.shared.b16 {%0,%1,%2,%3}, [%4];"
                 : "=r"(d[0]), "=r"(d[1]), "=r"(d[2]), "=r"(d[3]) : "r"(a));
}
#define CP_ASYNC(d, s) asm volatile("cp.async.ca.shared.global [%0], [%1], 16;" :: "r"(d), "l"(s) : "memory")
#define CP_COMMIT()    asm volatile("cp.async.commit_group;" ::: "memory")
#define CP_WAIT1()     asm volatile("cp.async.wait_group 1;" ::: "memory")

__device__ __forceinline__ uint32_t h2_pack(float a, float b) {
    __half2 h = __floats2half2_rn(a, b);
    return *(uint32_t*)&h;
}

// ------ fused stats+split, 4 rows per block (MLP=4):
//        blocks 0..2047 -> H rows, 2048..2303 -> U rows -------------------------
__global__ void k_stats(const float* __restrict__ H, const float* __restrict__ U,
                        const float* __restrict__ wq, const float* __restrict__ bq,
                        const float* __restrict__ wc, const float* __restrict__ bc,
                        const float* __restrict__ wqc) {
    const int t = threadIdx.x;
    const int lane = t & 31, wid = t >> 5;
    __shared__ float sp[8][4], sm2[8][4];
    if (blockIdx.x < C_LEN / 4) {
        const int c0 = blockIdx.x * 4;
        // front-batched loads (MLP=4)
        float4 h[4];
#pragma unroll
        for (int r = 0; r < 4; ++r)
            h[r] = *(const float4*)(H + (size_t)(c0 + r) * 1024 + t * 4);
        const float4 w = ((const float4*)wc)[t];
        float p[4], m[4];
#pragma unroll
        for (int r = 0; r < 4; ++r) {
            *(uint2*)((uint16_t*)g_Hh + (size_t)(c0 + r) * 1024 + t * 4) =
                make_uint2(h2_pack(h[r].x, h[r].y), h2_pack(h[r].z, h[r].w));
            p[r] = h[r].x * w.x + h[r].y * w.y + h[r].z * w.z + h[r].w * w.w;
            m[r] = fmaxf(fmaxf(h[r].x, h[r].y), fmaxf(h[r].z, h[r].w));
        }
#pragma unroll
        for (int o = 16; o; o >>= 1)
#pragma unroll
            for (int r = 0; r < 4; ++r) {
                p[r] += __shfl_down_sync(0xffffffffu, p[r], o);
                m[r] = fmaxf(m[r], __shfl_down_sync(0xffffffffu, m[r], o));
            }
        if (lane == 0)
#pragma unroll
            for (int r = 0; r < 4; ++r) { sp[wid][r] = p[r]; sm2[wid][r] = m[r]; }
        __syncthreads();
        if (t < 4) {
            float pp = sp[0][t], mm = sm2[0][t];
#pragma unroll
            for (int i = 1; i < 8; ++i) { pp += sp[i][t]; mm = fmaxf(mm, sm2[i][t]); }
            g_cterm[c0 + t] = pp + bc[0];
            g_bmax[c0 + t] = mm;
        }
    } else {
        const int n0 = (blockIdx.x - C_LEN / 4) * 4;
        float4 u[4];
#pragma unroll
        for (int r = 0; r < 4; ++r)
            u[r] = *(const float4*)(U + (size_t)(n0 + r) * 1024 + t * 4);
        const float4 w = ((const float4*)wq)[t];
        const float4 w2 = ((const float4*)wqc)[t];
        float p[4];
#pragma unroll
        for (int r = 0; r < 4; ++r) {
            *(uint2*)((uint16_t*)g_B1 + (size_t)(n0 + r) * 1024 + t * 4) =
                make_uint2(h2_pack(32.f * u[r].x * w2.x, 32.f * u[r].y * w2.y),
                           h2_pack(32.f * u[r].z * w2.z, 32.f * u[r].w * w2.w));
            p[r] = u[r].x * w.x + u[r].y * w.y + u[r].z * w.z + u[r].w * w.w;
        }
#pragma unroll
        for (int o = 16; o; o >>= 1)
#pragma unroll
            for (int r = 0; r < 4; ++r) p[r] += __shfl_down_sync(0xffffffffu, p[r], o);
        if (lane == 0)
#pragma unroll
            for (int r = 0; r < 4; ++r) sp[wid][r] = p[r];
        __syncthreads();
        if (t < 4) {
            float s = sp[0][t];
#pragma unroll
            for (int i = 1; i < 8; ++i) s += sp[i][t];
            g_qterm[n0 + t] = s + bq[0];
        }
    }
}

// ------- prep: Z_q reduction + transpose B2 = 16 * rz * U^T; block(0,0) also
//         computes the c2q softmax scalars {M, 1/Z} into g_mz ------------------
__global__ void k_prep_ut(const float* __restrict__ U) {
    __shared__ float t[32][33];
    __shared__ float srz[32];
    const int tid = threadIdx.x;
    const int tx = tid & 31, ty = tid >> 5;
    const int d0 = blockIdx.x * 32, q0 = blockIdx.y * 32;
    if (tid < 32) {
        float s = 0.f;
#pragma unroll
        for (int i = 0; i < 64; ++i) s += g_colpart[i * 1024 + q0 + tid];
        srz[tid] = 16.f / s;
    }
#pragma unroll
    for (int i = 0; i < 4; ++i)
        t[ty + 8 * i][tx] = U[(size_t)(q0 + ty + 8 * i) * 1024 + d0 + tx];
    __syncthreads();
#pragma unroll
    for (int i = 0; i < 4; ++i) {
        const int d = d0 + ty + 8 * i;
        const float v = t[tx][ty + 8 * i] * srz[tx];
        ((__half*)g_B2)[(size_t)d * 1024 + q0 + tx] = __float2half_rn(v);
    }

    if (blockIdx.x == 0 && blockIdx.y == 0) {
        __shared__ float sred[8];
        __shared__ float sm;
        const int lane = tid & 31, wid = tid >> 5;
        float m = -1e30f;
        for (int c = tid; c < C_LEN; c += 256) m = fmaxf(m, g_bmax[c]);
#pragma unroll
        for (int o = 16; o; o >>= 1) m = fmaxf(m, __shfl_xor_sync(0xffffffffu, m, o));
        if (lane == 0) sred[wid] = m;
        __syncthreads();
        if (tid == 0) {
            float v = sred[0];
#pragma unroll
            for (int i = 1; i < 8; ++i) v = fmaxf(v, sred[i]);
            sm = v;
        }
        __syncthreads();
        const float mm = sm;
        float z = 0.f;
        for (int c = tid; c < C_LEN; c += 256) z += __expf(g_bmax[c] - mm);
#pragma unroll
        for (int o = 16; o; o >>= 1) z += __shfl_xor_sync(0xffffffffu, z, o);
        if (lane == 0) sred[wid] = z;
        __syncthreads();
        if (tid == 0) {
            float v = sred[0];
#pragma unroll
            for (int i = 1; i < 8; ++i) v += sred[i];
            g_mz[0] = mm;
            g_mz[1] = 1.f / v;
        }
    }
}

// -------- GEMM: 3-stage cp.async, K=32/stage, 8 warps 64x32, 1 product --------
#define TS    16384u
#define O_B   8192u

__device__ __forceinline__ void fill_st(uint32_t sbuf, const __half* A, const __half* B,
                                        int m0, int n0, int k0, int t) {
#pragma unroll
    for (int u = 0; u < 2; ++u) {
        const int row = (t >> 2) + u * 64, ch = t & 3;
        const int chs = ch ^ ((row >> 1) & 3);
        const uint32_t d = sbuf + (uint32_t)(row * 64 + chs * 16);
        const size_t oa = (size_t)(m0 + row) * 1024 + k0 + ch * 8;
        const size_t ob = (size_t)(n0 + row) * 1024 + k0 + ch * 8;
        CP_ASYNC(d,       A + oa);
        CP_ASYNC(d + O_B, B + ob);
    }
}

// PASS=1: acc=32*s -> e=exp(s+..)/16 fp16 + col sums.
// PASS=2: store U_toggler fp32 + broadcast H_toggler slice.
template <int PASS>
__global__ __launch_bounds__(256, 2)
void k_mma(const __half* __restrict__ A, const __half* __restrict__ B,
           const float* __restrict__ bqc, float* __restrict__ out) {
    extern __shared__ char sm[];
    const uint32_t sb = smem_u32(sm);
    const int tid = threadIdx.x;
    const int lane = tid & 31, wid = tid >> 5;
    const int wm = wid & 1, wn = wid >> 1;
    const int g = lane >> 2, tq = lane & 3;
    const int m0 = blockIdx.y * 128, n0 = blockIdx.x * 128;
    const int lr = lane & 15, lc = lane >> 4;

    float4 acc[4][4];
#pragma unroll
    for (int i = 0; i < 4; ++i)
#pragma unroll
        for (int j = 0; j < 4; ++j) acc[i][j] = make_float4(0.f, 0.f, 0.f, 0.f);

    fill_st(sb, A, B, m0, n0, 0, tid);       CP_COMMIT();
    fill_st(sb + TS, A, B, m0, n0, 32, tid); CP_COMMIT();

    for (int s = 0; s < 32; ++s) {
        CP_WAIT1();
        __syncthreads();
        const uint32_t buf = sb + (uint32_t)(s % 3) * TS;

#pragma unroll
        for (int kk = 0; kk < 2; ++kk) {
            uint32_t af[4][4], bf[2][4];
#pragma unroll
            for (int mt = 0; mt < 4; ++mt) {
                const int row = wm * 64 + mt * 16 + lr;
                const int ch = kk * 2 + lc;
                const uint32_t off = (uint32_t)(row * 64 + ((ch ^ ((row >> 1) & 3)) * 16));
                ldsm4(af[mt], buf + off);
            }
#pragma unroll
            for (int nb = 0; nb < 2; ++nb) {
                const int row = wn * 32 + nb * 16 + lr;
                const int ch = kk * 2 + lc;
                const uint32_t off = (uint32_t)(row * 64 + ((ch ^ ((row >> 1) & 3)) * 16));
                ldsm4(bf[nb], buf + O_B + off);
            }
#pragma unroll
            for (int mt = 0; mt < 4; ++mt)
#pragma unroll
                for (int nt = 0; nt < 4; ++nt) {
                    const int nb = nt >> 1, p = nt & 1;
                    mma16816(acc[mt][nt], af[mt], bf[nb][p], bf[nb][p + 2]);
                }
        }

        if (s < 30)
            fill_st(sb + (uint32_t)((s + 2) % 3) * TS, A, B, m0, n0, (s + 2) * 32, tid);
        CP_COMMIT();
    }
    __syncthreads();

    if (PASS == 1) {
        const float bq = bqc[0];
        float* s_cp = (float*)sm;
        float cs[4][2];
#pragma unroll
        for (int nt = 0; nt < 4; ++nt) { cs[nt][0] = 0.f; cs[nt][1] = 0.f; }
#pragma unroll
        for (int mt = 0; mt < 4; ++mt) {
            const int row = m0 + wm * 64 + mt * 16 + g;
            const float ct0 = g_cterm[row], ct1 = g_cterm[row + 8];
#pragma unroll
            for (int nt = 0; nt < 4; ++nt) {
                const int col = n0 + wn * 32 + nt * 8 + tq * 2;
                const float q0 = g_qterm[col] + bq, q1 = g_qterm[col + 1] + bq;
                const float4 c = acc[mt][nt];
                const float e00 = __expf(c.x * 0.03125f + ct0 + q0);
                const float e01 = __expf(c.y * 0.03125f + ct0 + q1);
                const float e10 = __expf(c.z * 0.03125f + ct1 + q0);
                const float e11 = __expf(c.w * 0.03125f + ct1 + q1);
                const size_t o0 = (size_t)row * 1024 + col;
                const size_t o1 = (size_t)(row + 8) * 1024 + col;
                *(uint32_t*)((uint16_t*)g_e + o0) = h2_pack(e00 * 0.0625f, e01 * 0.0625f);
                *(uint32_t*)((uint16_t*)g_e + o1) = h2_pack(e10 * 0.0625f, e11 * 0.0625f);
                cs[nt][0] += e00 + e10;
                cs[nt][1] += e01 + e11;
            }
        }
#pragma unroll
        for (int nt = 0; nt < 4; ++nt)
#pragma unroll
            for (int o = 4; o < 32; o <<= 1) {
                cs[nt][0] += __shfl_xor_sync(0xffffffffu, cs[nt][0], o);
                cs[nt][1] += __shfl_xor_sync(0xffffffffu, cs[nt][1], o);
            }
        if (g == 0) {
#pragma unroll
            for (int nt = 0; nt < 4; ++nt) {
                const int col = wn * 32 + nt * 8 + tq * 2;
                s_cp[wm * 128 + col] = cs[nt][0];
                s_cp[wm * 128 + col + 1] = cs[nt][1];
            }
        }
        __syncthreads();
        if (tid < 128) {
            const float v = s_cp[tid] + s_cp[128 + tid];
            g_colpart[blockIdx.y * 1024 + n0 + tid] = v;
        }
    } else {
#pragma unroll
        for (int mt = 0; mt < 4; ++mt) {
            const int row = m0 + wm * 64 + mt * 16 + g;
#pragma unroll
            for (int nt = 0; nt < 4; ++nt) {
                const int col = n0 + wn * 32 + nt * 8 + tq * 2;
                const float4 c = acc[mt][nt];
                *(float2*)(out + (size_t)row * 1024 + col) = make_float2(c.x, c.y);
                *(float2*)(out + (size_t)(row + 8) * 1024 + col) = make_float2(c.z, c.w);
            }
        }
        const float4 hv = *(const float4*)(g_hrow + n0 + (tid & 31) * 4);
        float* o2 = out + (size_t)C_LEN * 1024;
#pragma unroll
        for (int r = tid >> 5; r < 128; r += 8)
            *(float4*)(o2 + (size_t)(m0 + r) * 1024 + n0 + (tid & 31) * 4) = hv;
    }
}

// ----- weighted column sum of fp16 H (256 chunks x 32 rows), scalars hoisted -----
__global__ void k_hpart() {
    const int chunk = blockIdx.x, t = threadIdx.x;
    const float mm = g_mz[0], rz = g_mz[1];
    float4 a = make_float4(0.f, 0.f, 0.f, 0.f);
    const int c0 = chunk * 32;
#pragma unroll 8
    for (int c = c0; c < c0 + 32; ++c) {
        const float wv = __expf(g_bmax[c] - mm) * rz;
        const uint2 hv = *(const uint2*)((const uint16_t*)g_Hh + (size_t)c * 1024 + t * 4);
        const float2 h01 = __half22float2(*(const __half2*)&hv.x);
        const float2 h23 = __half22float2(*(const __half2*)&hv.y);
        a.x = fmaf(wv, h01.x, a.x);
        a.y = fmaf(wv, h01.y, a.y);
        a.z = fmaf(wv, h23.x, a.z);
        a.w = fmaf(wv, h23.y, a.w);
    }
    *(float4*)(&g_hpart[chunk][t * 4]) = a;
}

__global__ void k_hred() {
    const int d = blockIdx.x * 64 + threadIdx.x;
    float s = 0.f;
#pragma unroll
    for (int i = 0; i < 256; ++i) s += g_hpart[i][d];
    g_hrow[d] = s;
}

// ---------------- launch ----------------------------------------------------------
extern "C" void kernel_launch(void* const* d_in, const int* in_sizes, int n_in,
                              void* d_out, int out_size) {
    const float* H   = (const float*)d_in[0];
    const float* U   = (const float*)d_in[1];
    const float* wq  = (const float*)d_in[2];
    const float* bq  = (const float*)d_in[3];
    const float* wc  = (const float*)d_in[4];
    const float* bc  = (const float*)d_in[5];
    const float* wqc = (const float*)d_in[6];
    const float* bqc = (const float*)d_in[7];
    float* out = (float*)d_out;

    static bool s_attr = false;
    if (!s_attr) {
        cudaFuncSetAttribute(k_mma<1>, cudaFuncAttributeMaxDynamicSharedMemorySize, 3 * TS);
        cudaFuncSetAttribute(k_mma<2>, cudaFuncAttributeMaxDynamicSharedMemorySize, 3 * TS);
        s_attr = true;
    }

    void *hh, *b1, *b2, *ee;
    cudaGetSymbolAddress(&hh, g_Hh);
    cudaGetSymbolAddress(&b1, g_B1);
    cudaGetSymbolAddress(&b2, g_B2);
    cudaGetSymbolAddress(&ee, g_e);

    k_stats<<<(C_LEN + Q_LEN) / 4, 256>>>(H, U, wq, bq, wc, bc, wqc);
    k_mma<1><<<dim3(8, 64), 256, 3 * TS>>>((const __half*)hh, (const __half*)b1, bqc, nullptr);
    k_prep_ut<<<dim3(32, 32), 256>>>(U);
    k_hpart<<<256, 256>>>();
    k_hred<<<16, 64>>>();
    k_mma<2><<<dim3(8, 64), 256, 3 * TS>>>((const __half*)ee, (const __half*)b2, bqc, out);
}